// round 8
// baseline (speedup 1.0000x reference)
#include <cuda_runtime.h>
#include <cstdint>

#define BB 4096
#define DD 512
#define CJ 75                   // j's per chunk (compile-time trip; last chunk padded)
#define NCHUNK 55               // 55*75 = 4125 >= 4096; grid 16x55 = 880 ~= 2 waves @ occ 3
#define NIG 16
#define NBLK (NIG * NCHUNK)     // 880

#define LOG2E_F   1.4426950408889634f
#define LN2_F     0.6931471805599453f
#define LOG_2PI_F 1.8378770664093453f
#define NEG_INF_F (__int_as_float(0xff800000))

typedef unsigned long long ull;

// ---- static scratch ----
__device__ float g_part[(size_t)NCHUNK * 17 * BB]; // [chunk][acc][i]
__device__ float g_Mc[NCHUNK * 17];                // per-chunk per-acc max
__device__ float g_lse[17 * BB];                   // per-acc per-i log2-LSE
__device__ float g_tcpart[NIG];
__device__ float g_reconpart[512];
__device__ int   g_ctr;

__device__ __forceinline__ float ex2f(float x) {
    float y; asm("ex2.approx.ftz.f32 %0, %1;" : "=f"(y) : "f"(x)); return y;
}
__device__ __forceinline__ float lg2f(float x) {
    float y; asm("lg2.approx.f32 %0, %1;" : "=f"(y) : "f"(x)); return y;
}
__device__ __forceinline__ ull fma2(ull a, ull b, ull c) {
    ull d; asm("fma.rn.f32x2 %0, %1, %2, %3;" : "=l"(d) : "l"(a), "l"(b), "l"(c)); return d;
}
__device__ __forceinline__ ull add2(ull a, ull b) {
    ull d; asm("add.rn.f32x2 %0, %1, %2;" : "=l"(d) : "l"(a), "l"(b)); return d;
}
__device__ __forceinline__ ull mul2(ull a, ull b) {
    ull d; asm("mul.rn.f32x2 %0, %1, %2;" : "=l"(d) : "l"(a), "l"(b)); return d;
}
__device__ __forceinline__ ull pack2(float lo, float hi) {
    ull d; asm("mov.b64 %0, {%1, %2};" : "=l"(d) : "f"(lo), "f"(hi)); return d;
}
__device__ __forceinline__ void unpack2(ull v, float& lo, float& hi) {
    asm("mov.b64 {%0, %1}, %2;" : "=f"(lo), "=f"(hi) : "l"(v));
}

// packed exp2 via poly: fma-pipe for poly, alu-pipe (shift/add) for scale build.
// exp2(f) ~ 1 + f*(P1 + f*(P2 + f*(P3 + f*P4))); result = scale + q*scale.
__device__ __forceinline__ ull poly_exp2(ull v, ull MAGIC2, ull NMAGIC2, ull NONE2,
                                         ull P4, ull P3, ull P2, ull P1) {
    ull t   = add2(v, MAGIC2);       // RN -> int in low mantissa
    ull ipf = add2(t, NMAGIC2);      // i as float (exact)
    ull f   = fma2(ipf, NONE2, v);   // f = v - i in [-0.5, 0.5]
    ull p   = fma2(P4, f, P3);
    p = fma2(p, f, P2);
    p = fma2(p, f, P1);
    ull q = mul2(p, f);
    uint32_t blo, bhi;
    asm("mov.b64 {%0, %1}, %2;" : "=r"(blo), "=r"(bhi) : "l"(t));
    blo = (blo > 0x4B3FFF88u) ? blo : 0x4B3FFF88u;   // clamp i >= -120
    bhi = (bhi > 0x4B3FFF88u) ? bhi : 0x4B3FFF88u;
    uint32_t sl = (blo << 23) + 0x3F800000u;         // 2^i bits (alu: SHF+IADD3)
    uint32_t sh = (bhi << 23) + 0x3F800000u;
    ull scale;
    asm("mov.b64 %0, {%1, %2};" : "=l"(scale) : "r"(sl), "r"(sh));
    return fma2(q, scale, scale);
}

// ---------------------------------------------------------------------------
// K1: per-chunk coefficients + per-chunk max, hot pairwise loop, fused
// recon-MAE slices. Grid (16, 55), 256 thr, occ 3 -> ~2 waves at 444 slots.
// ---------------------------------------------------------------------------
__global__ void __launch_bounds__(256, 3)
k_main(const float* __restrict__ z, const float* __restrict__ data,
       const float* __restrict__ rec, const float* __restrict__ zm,
       const float* __restrict__ lv) {
    __shared__ __align__(16) float smc[CJ * 48];
    __shared__ float sM[17];
    __shared__ float sred[8][16];
    __shared__ float sredr[256];

    const int ig = blockIdx.x, ch = blockIdx.y, tid = threadIdx.x;
    const int jbase = ch * CJ;

    // fused recon MAE slice (first 512 blocks take one 4096-float slice each)
    const int blin = ch * NIG + ig;  // 0..879
    float racc = 0.f;
    if (blin < 512) {
        const float4* da = (const float4*)(data + (size_t)blin * 4096);
        const float4* rb = (const float4*)(rec  + (size_t)blin * 4096);
#pragma unroll
        for (int q = 0; q < 4; q++) {
            float4 a = da[tid + q * 256], b = rb[tid + q * 256];
            racc += (fabsf(a.x - b.x) + fabsf(a.y - b.y)) + (fabsf(a.z - b.z) + fabsf(a.w - b.w));
        }
    }

    // per-chunk coefficients (log2 domain) + per-l max of b2; pads (j>=BB) -> ~0 exps
    float b2max = NEG_INF_F;
    for (int idx = tid; idx < CJ * 16; idx += 256) {
        int jl = idx >> 4, l = idx & 15;
        int j = jbase + jl;
        float c0 = -200.f, c1 = 0.f, c2v = 0.f;
        if (j < BB) {
            float m  = zm[j * 16 + l];
            float v  = lv[j * 16 + l];
            float a2 = -0.5f * LOG2E_F * __expf(-v);
            float b2 = -0.5f * LOG2E_F * (v + LOG_2PI_F);
            c0 = fmaf(a2, m * m, b2);
            c1 = -2.0f * a2 * m;
            c2v = a2;
            b2max = fmaxf(b2max, b2);
        }
        smc[jl * 48 + l]      = c0;
        smc[jl * 48 + 16 + l] = c1;
        smc[jl * 48 + 32 + l] = c2v;
    }
    // lanes l and l^16 hold the same latent (stride 256 ≡ 0 mod 16)
    b2max = fmaxf(b2max, __shfl_xor_sync(0xffffffffu, b2max, 16));
    if ((tid & 16) == 0) sred[tid >> 5][tid & 15] = b2max;
    __syncthreads();
    if (tid < 16) {
        float m = NEG_INF_F;
#pragma unroll
        for (int w = 0; w < 8; w++) m = fmaxf(m, sred[w][tid]);
        sM[tid] = m;
    }
    __syncthreads();
    if (tid == 0) {
        float s = 0.f;
#pragma unroll
        for (int l = 0; l < 16; l++) s += sM[l];
        sM[16] = s;
    }
    // fold -M_l into c0
    for (int idx = tid; idx < CJ * 16; idx += 256) {
        int jl = idx >> 4, l = idx & 15;
        smc[jl * 48 + l] -= sM[l];
    }
    __syncthreads();
    if (tid < 17) g_Mc[ch * 17 + tid] = sM[tid];

    // this thread's i-row of z as packed f32x2
    const int i = ig * 256 + tid;
    ull zz[8], z2[8];
    {
        const ulonglong2* zp = (const ulonglong2*)(z + (size_t)i * 16);
#pragma unroll
        for (int q = 0; q < 4; q++) { ulonglong2 t = zp[q]; zz[2*q] = t.x; zz[2*q+1] = t.y; }
#pragma unroll
        for (int g = 0; g < 8; g++) z2[g] = mul2(zz[g], zz[g]);
    }

    const ull MAGIC2  = pack2( 12582912.f,  12582912.f);
    const ull NMAGIC2 = pack2(-12582912.f, -12582912.f);
    const ull NONE2   = pack2(-1.f, -1.f);
    const ull P4 = pack2(0.009618129f, 0.009618129f);
    const ull P3 = pack2(0.055504109f, 0.055504109f);
    const ull P2 = pack2(0.240226507f, 0.240226507f);
    const ull P1 = pack2(0.693147181f, 0.693147181f);

    ull s[8];
#pragma unroll
    for (int g = 0; g < 8; g++) s[g] = pack2(0.f, 0.f);
    float s16 = 0.f;

    for (int jj = 0; jj < CJ; jj++) {
        const ulonglong2* C = (const ulonglong2*)(smc + jj * 48);
        ull e[8];
#pragma unroll
        for (int h = 0; h < 4; h++) {
            ulonglong2 c0 = C[h], c1 = C[4 + h], c2 = C[8 + h];
            ull va = fma2(c2.x, z2[2*h],   fma2(c1.x, zz[2*h],   c0.x));
            ull vb = fma2(c2.y, z2[2*h+1], fma2(c1.y, zz[2*h+1], c0.y));
            if (h < 3) {   // 12 MUFU exps
                float al, ah, bl, bh;
                unpack2(va, al, ah); unpack2(vb, bl, bh);
                e[2*h]   = pack2(ex2f(al), ex2f(ah));
                e[2*h+1] = pack2(ex2f(bl), ex2f(bh));
            } else {       // 4 poly exps on fma/alu pipes
                e[6] = poly_exp2(va, MAGIC2, NMAGIC2, NONE2, P4, P3, P2, P1);
                e[7] = poly_exp2(vb, MAGIC2, NMAGIC2, NONE2, P4, P3, P2, P1);
            }
            s[2*h]   = add2(s[2*h],   e[2*h]);
            s[2*h+1] = add2(s[2*h+1], e[2*h+1]);
        }
        // exp2(sum_l v_l) = product of per-latent exps
        ull m0 = mul2(e[0], e[1]), m1 = mul2(e[2], e[3]);
        ull m2 = mul2(e[4], e[5]), m3 = mul2(e[6], e[7]);
        ull mm = mul2(mul2(m0, m1), mul2(m2, m3));
        float pa, pb; unpack2(mm, pa, pb);
        s16 = fmaf(pa, pb, s16);
    }

    // coalesced partial writes: [chunk][acc][i]
    float* gp = g_part + (size_t)ch * 17 * BB;
#pragma unroll
    for (int g = 0; g < 8; g++) {
        float lo, hi; unpack2(s[g], lo, hi);
        gp[(size_t)(2*g)   * BB + i] = lo;
        gp[(size_t)(2*g+1) * BB + i] = hi;
    }
    gp[(size_t)16 * BB + i] = s16;

    // recon block reduction
    sredr[tid] = racc;
    __syncthreads();
    for (int st = 128; st > 0; st >>= 1) {
        if (tid < st) sredr[tid] += sredr[tid + st];
        __syncthreads();
    }
    if (tid == 0 && blin < 512) g_reconpart[blin] = sredr[0];
}

// ---------------------------------------------------------------------------
// K2: parallel weighted chunk merge. Thread owns (a, i): 55 coalesced loads in
// 4 independent fixed-order chains (deterministic), weighted by 2^(Mc-Mmax).
// ---------------------------------------------------------------------------
__global__ void __launch_bounds__(256) k_merge() {
    __shared__ float sw[NCHUNK];
    __shared__ float sMmax;
    const int a = blockIdx.x;     // 0..16
    const int ig = blockIdx.y;    // 0..15
    const int tid = threadIdx.x;

    if (tid == 0) {
        float m = NEG_INF_F;
#pragma unroll
        for (int c = 0; c < NCHUNK; c++) m = fmaxf(m, g_Mc[c * 17 + a]);
        sMmax = m;
    }
    __syncthreads();
    if (tid < NCHUNK) sw[tid] = ex2f(g_Mc[tid * 17 + a] - sMmax);
    __syncthreads();

    const int i = ig * 256 + tid;
    float a0 = 0.f, a1 = 0.f, a2 = 0.f, a3 = 0.f;
#pragma unroll
    for (int c = 0; c < 14; c++) {
        a0 = fmaf(g_part[((size_t)(c)      * 17 + a) * BB + i], sw[c],      a0);
        a1 = fmaf(g_part[((size_t)(c + 14) * 17 + a) * BB + i], sw[c + 14], a1);
        a2 = fmaf(g_part[((size_t)(c + 28) * 17 + a) * BB + i], sw[c + 28], a2);
        if (c < 13)
            a3 = fmaf(g_part[((size_t)(c + 42) * 17 + a) * BB + i], sw[c + 42], a3);
    }
    float acc = (a0 + a1) + (a2 + a3);
    g_lse[a * BB + i] = sMmax + lg2f(acc);   // log2 units
}

// ---------------------------------------------------------------------------
// K3: per-i combine (tc + KL), block sums, last-block final scalar.
// ---------------------------------------------------------------------------
__global__ void __launch_bounds__(256) k_fin(const float* __restrict__ zm,
                                             const float* __restrict__ lv,
                                             float* __restrict__ out) {
    __shared__ float sm[256];
    __shared__ int isLast;
    const int tid = threadIdx.x;
    const int i = blockIdx.x * 256 + tid;

    float prod = 0.f;
#pragma unroll
    for (int l = 0; l < 16; l++) prod += g_lse[l * BB + i];
    float tc = (g_lse[16 * BB + i] - prod) * LN2_F;

    float kl = 0.f;
#pragma unroll
    for (int l = 0; l < 16; l++) {
        float m = zm[i * 16 + l], v = lv[i * 16 + l];
        kl += fmaf(m, m, __expf(v)) - v - 1.0f;
    }
    float val = tc + 0.5f * kl;

    sm[tid] = val;
    __syncthreads();
    for (int st = 128; st > 0; st >>= 1) {
        if (tid < st) sm[tid] += sm[tid + st];
        __syncthreads();
    }
    if (tid == 0) g_tcpart[blockIdx.x] = sm[0];

    // last-block final combine (counter self-resets => replay-safe)
    if (tid == 0) {
        __threadfence();
        int prev = atomicAdd(&g_ctr, 1);
        isLast = (prev == (int)gridDim.x - 1);
    }
    __syncthreads();
    if (!isLast) return;
    __threadfence();

    sm[tid] = g_reconpart[tid] + g_reconpart[tid + 256];
    __syncthreads();
    for (int st = 128; st > 0; st >>= 1) {
        if (tid < st) sm[tid] += sm[tid + st];
        __syncthreads();
    }
    float recon = sm[0];
    __syncthreads();
    sm[tid] = (tid < NIG) ? g_tcpart[tid] : 0.f;
    __syncthreads();
    for (int st = 128; st > 0; st >>= 1) {
        if (tid < st) sm[tid] += sm[tid + st];
        __syncthreads();
    }
    if (tid == 0) {
        out[0] = recon / (float)(BB * DD) + sm[0] / (float)BB;
        g_ctr = 0;
    }
}

extern "C" void kernel_launch(void* const* d_in, const int* in_sizes, int n_in,
                              void* d_out, int out_size) {
    const float* data = (const float*)d_in[0];
    const float* rec  = (const float*)d_in[1];
    const float* z    = (const float*)d_in[2];
    const float* zm   = (const float*)d_in[3];
    const float* lv   = (const float*)d_in[4];
    float* out = (float*)d_out;

    dim3 g(NIG, NCHUNK);
    k_main <<<g, 256>>>(z, data, rec, zm, lv);
    dim3 gm(17, NIG);
    k_merge<<<gm, 256>>>();
    k_fin  <<<BB / 256, 256>>>(zm, lv, out);
}

// round 9
// speedup vs baseline: 1.1370x; 1.1370x over previous
#include <cuda_runtime.h>
#include <cstdint>

#define BB 4096
#define DD 512
#define CJ 111                  // j's per chunk
#define NCHUNK 37               // grid 16 x 37 = 592 = 2 exact waves @ occ 2
#define NIG 16

#define LOG2E_F   1.4426950408889634f
#define LN2_F     0.6931471805599453f
#define LOG_2PI_F 1.8378770664093453f
#define NEG_INF_F (__int_as_float(0xff800000))

typedef unsigned long long ull;

// ---- static scratch ----
__device__ float g_part[(size_t)NCHUNK * 17 * BB]; // [chunk][acc][i]
__device__ float g_Mc[NCHUNK * 17];                // per-chunk per-acc max
__device__ float g_lse[17 * BB];                   // per-acc per-i log2-LSE
__device__ float g_tcpart[NIG];
__device__ float g_reconpart[512];
__device__ int   g_ctr;

__device__ __forceinline__ float ex2f(float x) {
    float y; asm("ex2.approx.ftz.f32 %0, %1;" : "=f"(y) : "f"(x)); return y;
}
__device__ __forceinline__ float lg2f(float x) {
    float y; asm("lg2.approx.f32 %0, %1;" : "=f"(y) : "f"(x)); return y;
}
__device__ __forceinline__ ull fma2(ull a, ull b, ull c) {
    ull d; asm("fma.rn.f32x2 %0, %1, %2, %3;" : "=l"(d) : "l"(a), "l"(b), "l"(c)); return d;
}
__device__ __forceinline__ ull add2(ull a, ull b) {
    ull d; asm("add.rn.f32x2 %0, %1, %2;" : "=l"(d) : "l"(a), "l"(b)); return d;
}
__device__ __forceinline__ ull mul2(ull a, ull b) {
    ull d; asm("mul.rn.f32x2 %0, %1, %2;" : "=l"(d) : "l"(a), "l"(b)); return d;
}
__device__ __forceinline__ ull pack2(float lo, float hi) {
    ull d; asm("mov.b64 %0, {%1, %2};" : "=l"(d) : "f"(lo), "f"(hi)); return d;
}
__device__ __forceinline__ void unpack2(ull v, float& lo, float& hi) {
    asm("mov.b64 {%0, %1}, %2;" : "=f"(lo), "=f"(hi) : "l"(v));
}

// packed exp2 via poly on fma/alu pipes (clamped below at 2^-120)
__device__ __forceinline__ ull poly_exp2(ull v, ull MAGIC2, ull NMAGIC2, ull NONE2,
                                         ull ONE2, ull P4, ull P3, ull P2, ull P1) {
    ull t   = add2(v, MAGIC2);
    ull ipf = add2(t, NMAGIC2);
    ull f   = fma2(ipf, NONE2, v);
    ull p   = fma2(P4, f, P3);
    p = fma2(p, f, P2);
    p = fma2(p, f, P1);
    p = fma2(p, f, ONE2);
    uint32_t blo, bhi;
    asm("mov.b64 {%0, %1}, %2;" : "=r"(blo), "=r"(bhi) : "l"(t));
    blo = (blo > 0x4B3FFF88u) ? blo : 0x4B3FFF88u;
    bhi = (bhi > 0x4B3FFF88u) ? bhi : 0x4B3FFF88u;
    uint32_t sl = blo * 8388608u + 0x3F800000u;
    uint32_t sh = bhi * 8388608u + 0x3F800000u;
    ull scale;
    asm("mov.b64 %0, {%1, %2};" : "=l"(scale) : "r"(sl), "r"(sh));
    return mul2(p, scale);
}

// ---------------------------------------------------------------------------
// K1: per-chunk coefficients + per-chunk max, hot pairwise loop (Horner form),
// fused recon-MAE slice. Grid (16, 37), 256 thr, occ 2 -> 2 exact waves.
// ---------------------------------------------------------------------------
__global__ void __launch_bounds__(256, 2)
k_main(const float* __restrict__ z, const float* __restrict__ data,
       const float* __restrict__ rec, const float* __restrict__ zm,
       const float* __restrict__ lv) {
    __shared__ __align__(16) float smc[CJ * 48];
    __shared__ float sM[17];
    __shared__ float sred[8][16];
    __shared__ float sredr[256];

    const int ig = blockIdx.x, ch = blockIdx.y, tid = threadIdx.x;
    const int jbase = ch * CJ;
    const int jcnt = (BB - jbase < CJ) ? (BB - jbase) : CJ;

    // fused recon MAE slice
    const int blin = ch * NIG + ig;  // 0..591
    float racc = 0.f;
    if (blin < 512) {
        const float4* da = (const float4*)(data + (size_t)blin * 4096);
        const float4* rb = (const float4*)(rec  + (size_t)blin * 4096);
#pragma unroll
        for (int q = 0; q < 4; q++) {
            float4 a = da[tid + q * 256], b = rb[tid + q * 256];
            racc += (fabsf(a.x - b.x) + fabsf(a.y - b.y)) + (fabsf(a.z - b.z) + fabsf(a.w - b.w));
        }
    }

    // per-chunk coefficients (log2 domain) + per-l max of b2 (exact)
    float b2max = NEG_INF_F;
    for (int idx = tid; idx < jcnt * 16; idx += 256) {
        int jl = idx >> 4, l = idx & 15;
        float m  = zm[jbase * 16 + idx];
        float v  = lv[jbase * 16 + idx];
        float a2 = -0.5f * LOG2E_F * __expf(-v);
        float b2 = -0.5f * LOG2E_F * (v + LOG_2PI_F);
        smc[jl * 48 + l]      = fmaf(a2, m * m, b2);
        smc[jl * 48 + 16 + l] = -2.0f * a2 * m;
        smc[jl * 48 + 32 + l] = a2;
        b2max = fmaxf(b2max, b2);
    }
    // lanes l and l^16 hold the same latent (stride 256 ≡ 0 mod 16)
    b2max = fmaxf(b2max, __shfl_xor_sync(0xffffffffu, b2max, 16));
    if ((tid & 16) == 0) sred[tid >> 5][tid & 15] = b2max;
    __syncthreads();
    if (tid < 16) {
        float m = NEG_INF_F;
#pragma unroll
        for (int w = 0; w < 8; w++) m = fmaxf(m, sred[w][tid]);
        sM[tid] = m;
    }
    __syncthreads();
    if (tid == 0) {
        float s = 0.f;
#pragma unroll
        for (int l = 0; l < 16; l++) s += sM[l];
        sM[16] = s;
    }
    // fold -M_l into c0
    for (int idx = tid; idx < jcnt * 16; idx += 256) {
        int jl = idx >> 4, l = idx & 15;
        smc[jl * 48 + l] -= sM[l];
    }
    __syncthreads();
    if (tid < 17) g_Mc[ch * 17 + tid] = sM[tid];

    // this thread's i-row of z as packed f32x2 (Horner form: no z^2 array)
    const int i = ig * 256 + tid;
    ull zz[8];
    {
        const ulonglong2* zp = (const ulonglong2*)(z + (size_t)i * 16);
#pragma unroll
        for (int q = 0; q < 4; q++) { ulonglong2 t = zp[q]; zz[2*q] = t.x; zz[2*q+1] = t.y; }
    }

    const ull MAGIC2  = pack2( 12582912.f,  12582912.f);
    const ull NMAGIC2 = pack2(-12582912.f, -12582912.f);
    const ull NONE2   = pack2(-1.f, -1.f);
    const ull ONE2    = pack2( 1.f,  1.f);
    const ull P4 = pack2(0.009618129f, 0.009618129f);
    const ull P3 = pack2(0.055504109f, 0.055504109f);
    const ull P2 = pack2(0.240226507f, 0.240226507f);
    const ull P1 = pack2(0.693147181f, 0.693147181f);

    ull s[8];
#pragma unroll
    for (int g = 0; g < 8; g++) s[g] = pack2(0.f, 0.f);
    float s16 = 0.f;

    for (int jj = 0; jj < jcnt; jj++) {
        const ulonglong2* C = (const ulonglong2*)(smc + jj * 48);
        ull e[8];
#pragma unroll
        for (int h = 0; h < 4; h++) {
            ulonglong2 c0 = C[h], c1 = C[4 + h], c2 = C[8 + h];
            // Horner: v = (a2*z + c1)*z + c0
            ull va = fma2(fma2(c2.x, zz[2*h],   c1.x), zz[2*h],   c0.x);
            ull vb = fma2(fma2(c2.y, zz[2*h+1], c1.y), zz[2*h+1], c0.y);
            if (h < 3) {   // 12 MUFU exps
                float al, ah, bl, bh;
                unpack2(va, al, ah); unpack2(vb, bl, bh);
                e[2*h]   = pack2(ex2f(al), ex2f(ah));
                e[2*h+1] = pack2(ex2f(bl), ex2f(bh));
            } else {       // 4 poly exps on fma/alu pipes
                e[6] = poly_exp2(va, MAGIC2, NMAGIC2, NONE2, ONE2, P4, P3, P2, P1);
                e[7] = poly_exp2(vb, MAGIC2, NMAGIC2, NONE2, ONE2, P4, P3, P2, P1);
            }
            s[2*h]   = add2(s[2*h],   e[2*h]);
            s[2*h+1] = add2(s[2*h+1], e[2*h+1]);
        }
        // exp2(sum_l v_l) = product of per-latent exps
        ull m0 = mul2(e[0], e[1]), m1 = mul2(e[2], e[3]);
        ull m2 = mul2(e[4], e[5]), m3 = mul2(e[6], e[7]);
        ull mm = mul2(mul2(m0, m1), mul2(m2, m3));
        float pa, pb; unpack2(mm, pa, pb);
        s16 = fmaf(pa, pb, s16);
    }

    // coalesced partial writes: [chunk][acc][i]
    float* gp = g_part + (size_t)ch * 17 * BB;
#pragma unroll
    for (int g = 0; g < 8; g++) {
        float lo, hi; unpack2(s[g], lo, hi);
        gp[(size_t)(2*g)   * BB + i] = lo;
        gp[(size_t)(2*g+1) * BB + i] = hi;
    }
    gp[(size_t)16 * BB + i] = s16;

    // recon block reduction
    sredr[tid] = racc;
    __syncthreads();
    for (int st = 128; st > 0; st >>= 1) {
        if (tid < st) sredr[tid] += sredr[tid + st];
        __syncthreads();
    }
    if (tid == 0 && blin < 512) g_reconpart[blin] = sredr[0];
}

// ---------------------------------------------------------------------------
// K2: parallel weighted chunk merge. Thread owns (a, i): 37 coalesced loads in
// 3 independent fixed-order chains (deterministic), weighted by 2^(Mc-Mmax).
// ---------------------------------------------------------------------------
__global__ void __launch_bounds__(256) k_merge() {
    __shared__ float sw[NCHUNK];
    __shared__ float sMmax;
    const int a = blockIdx.x;     // 0..16
    const int ig = blockIdx.y;    // 0..15
    const int tid = threadIdx.x;

    if (tid == 0) {
        float m = NEG_INF_F;
#pragma unroll
        for (int c = 0; c < NCHUNK; c++) m = fmaxf(m, g_Mc[c * 17 + a]);
        sMmax = m;
    }
    __syncthreads();
    if (tid < NCHUNK) sw[tid] = ex2f(g_Mc[tid * 17 + a] - sMmax);
    __syncthreads();

    const int i = ig * 256 + tid;
    float a0 = 0.f, a1 = 0.f, a2 = 0.f;
#pragma unroll
    for (int c = 0; c < 13; c++) {
        a0 = fmaf(g_part[((size_t)(c)      * 17 + a) * BB + i], sw[c],      a0);
        if (c < 12) {
            a1 = fmaf(g_part[((size_t)(c + 13) * 17 + a) * BB + i], sw[c + 13], a1);
            a2 = fmaf(g_part[((size_t)(c + 25) * 17 + a) * BB + i], sw[c + 25], a2);
        }
    }
    float acc = (a0 + a1) + a2;
    g_lse[a * BB + i] = sMmax + lg2f(acc);   // log2 units
}

// ---------------------------------------------------------------------------
// K3: per-i combine (tc + KL), block sums, last-block final scalar.
// ---------------------------------------------------------------------------
__global__ void __launch_bounds__(256) k_fin(const float* __restrict__ zm,
                                             const float* __restrict__ lv,
                                             float* __restrict__ out) {
    __shared__ float sm[256];
    __shared__ int isLast;
    const int tid = threadIdx.x;
    const int i = blockIdx.x * 256 + tid;

    float prod = 0.f;
#pragma unroll
    for (int l = 0; l < 16; l++) prod += g_lse[l * BB + i];
    float tc = (g_lse[16 * BB + i] - prod) * LN2_F;

    float kl = 0.f;
#pragma unroll
    for (int l = 0; l < 16; l++) {
        float m = zm[i * 16 + l], v = lv[i * 16 + l];
        kl += fmaf(m, m, __expf(v)) - v - 1.0f;
    }
    float val = tc + 0.5f * kl;

    sm[tid] = val;
    __syncthreads();
    for (int st = 128; st > 0; st >>= 1) {
        if (tid < st) sm[tid] += sm[tid + st];
        __syncthreads();
    }
    if (tid == 0) g_tcpart[blockIdx.x] = sm[0];

    // last-block final combine (counter self-resets => replay-safe)
    if (tid == 0) {
        __threadfence();
        int prev = atomicAdd(&g_ctr, 1);
        isLast = (prev == (int)gridDim.x - 1);
    }
    __syncthreads();
    if (!isLast) return;
    __threadfence();

    sm[tid] = g_reconpart[tid] + g_reconpart[tid + 256];
    __syncthreads();
    for (int st = 128; st > 0; st >>= 1) {
        if (tid < st) sm[tid] += sm[tid + st];
        __syncthreads();
    }
    float recon = sm[0];
    __syncthreads();
    sm[tid] = (tid < NIG) ? g_tcpart[tid] : 0.f;
    __syncthreads();
    for (int st = 128; st > 0; st >>= 1) {
        if (tid < st) sm[tid] += sm[tid + st];
        __syncthreads();
    }
    if (tid == 0) {
        out[0] = recon / (float)(BB * DD) + sm[0] / (float)BB;
        g_ctr = 0;
    }
}

extern "C" void kernel_launch(void* const* d_in, const int* in_sizes, int n_in,
                              void* d_out, int out_size) {
    const float* data = (const float*)d_in[0];
    const float* rec  = (const float*)d_in[1];
    const float* z    = (const float*)d_in[2];
    const float* zm   = (const float*)d_in[3];
    const float* lv   = (const float*)d_in[4];
    float* out = (float*)d_out;

    dim3 g(NIG, NCHUNK);
    k_main <<<g, 256>>>(z, data, rec, zm, lv);
    dim3 gm(17, NIG);
    k_merge<<<gm, 256>>>();
    k_fin  <<<BB / 256, 256>>>(zm, lv, out);
}